// round 15
// baseline (speedup 1.0000x reference)
#include <cuda_runtime.h>
#include <cuda_fp16.h>
#include <mma.h>
#include <cstdint>
using namespace nvcuda;

// Problem constants (fixed by setup_inputs)
#define BATCH   32
#define SLEN    4096
#define DMODEL  512
#define NHEADS  8
#define HD      64
#define WIN     128
#define SHIFT   64
#define NWIN    1024          // total windows (BATCH * 32)

// ---------------------------------------------------------------------------
// Persistent fp16 arrays — all hi-only (calibrated rel_err ~7.0e-4).
// Q part of g_qkv_hi is pre-scaled by 0.125 (exact power-of-2 fold).
// ---------------------------------------------------------------------------
__device__ __align__(16) __half g_x_hi[(size_t)BATCH * SLEN * DMODEL];
__device__ __align__(16) __half g_win_hi[3 * DMODEL * DMODEL];
__device__ __align__(16) __half g_wout_hi[DMODEL * DMODEL];
__device__ __align__(16) __half g_qkv_hi[(size_t)3 * NWIN * NHEADS * WIN * HD];
__device__ __align__(16) __half g_o_hi[(size_t)NWIN * WIN * DMODEL];

// ---------------------------------------------------------------------------
// wmma fp16 types (projections only)
// ---------------------------------------------------------------------------
using HA  = wmma::fragment<wmma::matrix_a, 16, 16, 16, __half, wmma::row_major>;
using HBc = wmma::fragment<wmma::matrix_b, 16, 16, 16, __half, wmma::col_major>;
using CF  = wmma::fragment<wmma::accumulator, 16, 16, 16, float>;

__device__ __forceinline__ void hi_store4(const float4 v, __half* hi) {
    *reinterpret_cast<__half2*>(hi)     = __halves2half2(__float2half_rn(v.x), __float2half_rn(v.y));
    *reinterpret_cast<__half2*>(hi + 2) = __halves2half2(__float2half_rn(v.z), __float2half_rn(v.w));
}

// ---------------------------------------------------------------------------
// PTX helpers
// ---------------------------------------------------------------------------
__device__ __forceinline__ uint32_t smem_to_u32(const void* p) {
    uint32_t a;
    asm("{ .reg .u64 t; cvta.to.shared.u64 t, %1; cvt.u32.u64 %0, t; }" : "=r"(a) : "l"(p));
    return a;
}
#define CP_ASYNC16(su32, gptr) \
    asm volatile("cp.async.cg.shared.global [%0], [%1], 16;" :: "r"(su32), "l"(gptr) : "memory")
#define CP_COMMIT() asm volatile("cp.async.commit_group;" ::: "memory")
#define CP_WAIT(n)  asm volatile("cp.async.wait_group %0;" :: "n"(n) : "memory")

__device__ __forceinline__ void mma16816(float c[4], uint32_t a0, uint32_t a1,
                                         uint32_t a2, uint32_t a3,
                                         uint32_t b0, uint32_t b1) {
    asm volatile(
        "mma.sync.aligned.m16n8k16.row.col.f32.f16.f16.f32 "
        "{%0,%1,%2,%3}, {%4,%5,%6,%7}, {%8,%9}, {%0,%1,%2,%3};"
        : "+f"(c[0]), "+f"(c[1]), "+f"(c[2]), "+f"(c[3])
        : "r"(a0), "r"(a1), "r"(a2), "r"(a3), "r"(b0), "r"(b1));
}
__device__ __forceinline__ void ldmx2t(uint32_t& r0, uint32_t& r1, uint32_t saddr) {
    asm volatile("ldmatrix.sync.aligned.m8n8.x2.trans.shared.b16 {%0,%1}, [%2];"
                 : "=r"(r0), "=r"(r1) : "r"(saddr));
}

// ---------------------------------------------------------------------------
// Prep splits, single merged launch; 2 float4 per thread, streaming reads.
// ---------------------------------------------------------------------------
#define N4X  (BATCH * SLEN * DMODEL / 4)        // 16,777,216
#define N4WI (3 * DMODEL * DMODEL / 4)          // 196,608
#define N4WO (DMODEL * DMODEL / 4)              // 65,536
#define N4ALL (N4X + N4WI + N4WO)

__global__ void k_split_all(const float4* __restrict__ x,
                            const float4* __restrict__ w_in,
                            const float4* __restrict__ w_out) {
    const int i0 = (blockIdx.x * blockDim.x + threadIdx.x) * 2;
#pragma unroll
    for (int u = 0; u < 2; u++) {
        int i = i0 + u;
        if (i >= N4ALL) return;
        if (i < N4X) {
            hi_store4(__ldcs(&x[i]), g_x_hi + (size_t)i * 4);
        } else if (i < N4X + N4WI) {
            int k = i - N4X;
            hi_store4(__ldcs(&w_in[k]), g_win_hi + (size_t)k * 4);
        } else {
            int k = i - N4X - N4WI;
            hi_store4(__ldcs(&w_out[k]), g_wout_hi + (size_t)k * 4);
        }
    }
}

// ---------------------------------------------------------------------------
// Projection GEMM (frozen R7/R9 config): C[128x256] per CTA = Ah@Bh^T,
// cp.async 3-stage, 512 threads, warp grid 4x4, warp tile 32x64.
// MODE 0: A = rolled x, B = w_in -> g_qkv_hi (Q block pre-scaled 0.125), +b_in
// MODE 1: A = g_o_hi,  B = w_out -> fp32 out with roll(+shift), +b_out
// ---------------------------------------------------------------------------
#define STG_BYTES 55296
#define PROJ_SMEM (3 * STG_BYTES)

template <int MODE>
__global__ __launch_bounds__(512, 1) void k_proj(const float* __restrict__ bias,
                                                 float* __restrict__ outp) {
    extern __shared__ char smem[];
    const uint32_t sb0 = smem_to_u32(smem);
    float* Cs = (float*)smem;              // [128][264]

    const int tid  = threadIdx.x;
    const int warp = tid >> 5;
    const int wr = warp >> 2, wc = warp & 3;
    const int n0 = blockIdx.x * 256;
    const int w  = blockIdx.y;
    const int b  = w >> 5, j = w & 31;

    const __half* Asrc_h = (MODE == 0) ? g_x_hi : g_o_hi;
    const __half* Bsrc_h = (MODE == 0) ? g_win_hi : g_wout_hi;

    const size_t abase = (MODE == 0) ? ((size_t)b * SLEN) * DMODEL
                                     : ((size_t)w * WIN) * DMODEL;

    CF acc[2][4];
#pragma unroll
    for (int i = 0; i < 2; i++)
#pragma unroll
        for (int jj = 0; jj < 4; jj++) wmma::fill_fragment(acc[i][jj], 0.0f);

    auto load_chunk = [&](int c, int st) {
        const uint32_t sbase = sb0 + st * STG_BYTES;
        const size_t g = (size_t)c * 64;
#pragma unroll
        for (int q = 0; q < 2; q++) {          // A: 128 rows x 8 c16
            int idx = tid + q * 512;
            int row = idx >> 3, c16 = idx & 7;
            size_t ar;
            if (MODE == 0) {
                int sp = (j * WIN + row + SHIFT) & (SLEN - 1);   // roll(-shift)
                ar = abase + (size_t)sp * DMODEL + g + c16 * 8;
            } else {
                ar = abase + (size_t)row * DMODEL + g + c16 * 8;
            }
            CP_ASYNC16(sbase + (uint32_t)(row * 144 + c16 * 16), Asrc_h + ar);
        }
#pragma unroll
        for (int q = 0; q < 4; q++) {          // B: 256 rows x 8 c16
            int idx = tid + q * 512;
            int row = idx >> 3, c16 = idx & 7;
            size_t br = (size_t)(n0 + row) * DMODEL + g + c16 * 8;
            CP_ASYNC16(sbase + 18432 + (uint32_t)(row * 144 + c16 * 16), Bsrc_h + br);
        }
        CP_COMMIT();
    };

    load_chunk(0, 0);
    load_chunk(1, 1);

    for (int c = 0; c < 8; c++) {
        if (c < 7) CP_WAIT(1); else CP_WAIT(0);
        __syncthreads();
        if (c + 2 < 8) load_chunk(c + 2, (c + 2) % 3);

        const __half* Ah = (const __half*)(smem + (c % 3) * STG_BYTES);
        const __half* Bh = Ah + 9216;
#pragma unroll
        for (int ks = 0; ks < 4; ks++) {
            HA ah[2];
#pragma unroll
            for (int i = 0; i < 2; i++)
                wmma::load_matrix_sync(ah[i], Ah + (wr * 32 + i * 16) * 72 + ks * 16, 72);
#pragma unroll
            for (int jj = 0; jj < 4; jj++) {
                HBc bh;
                wmma::load_matrix_sync(bh, Bh + (wc * 64 + jj * 16) * 72 + ks * 16, 72);
#pragma unroll
                for (int i = 0; i < 2; i++)
                    wmma::mma_sync(acc[i][jj], ah[i], bh, acc[i][jj]);
            }
        }
    }
    __syncthreads();

#pragma unroll
    for (int i = 0; i < 2; i++)
#pragma unroll
        for (int jj = 0; jj < 4; jj++)
            wmma::store_matrix_sync(Cs + (wr * 32 + i * 16) * 264 + wc * 64 + jj * 16,
                                    acc[i][jj], 264, wmma::mem_row_major);
    __syncthreads();

#pragma unroll
    for (int it = 0; it < 16; it++) {
        int idx = tid + it * 512;
        int r = idx >> 6, cc = (idx & 63) * 4;
        float4 v;
        v.x = Cs[r * 264 + cc + 0] + bias[n0 + cc + 0];
        v.y = Cs[r * 264 + cc + 1] + bias[n0 + cc + 1];
        v.z = Cs[r * 264 + cc + 2] + bias[n0 + cc + 2];
        v.w = Cs[r * 264 + cc + 3] + bias[n0 + cc + 3];
        if (MODE == 0) {
            int gc = n0 + cc;
            int p = gc >> 9, hh = (gc >> 6) & 7, d = gc & 63;
            if (p == 0) {      // fold 1/sqrt(hd)=0.125 into Q (exact pow-2)
                v.x *= 0.125f; v.y *= 0.125f; v.z *= 0.125f; v.w *= 0.125f;
            }
            size_t o = ((((size_t)p * NWIN + w) * NHEADS + hh) * WIN + r) * HD + d;
            hi_store4(v, g_qkv_hi + o);
        } else {
            int sp = (j * WIN + r + SHIFT) & (SLEN - 1);   // roll(+shift)
            *(float4*)(outp + ((size_t)b * SLEN + sp) * DMODEL + n0 + cc) = v;
        }
    }
}

// ---------------------------------------------------------------------------
// Attention — register-resident softmax (PTX mma.m16n8k16, FA2-style).
// One CTA per (head, window), 256 threads (8 warps), 2 CTAs/SM.
// Q arrives pre-scaled by 0.125 (folded at proj0) -> no scale loop here.
// smem: Qh [128][72] @0, Kh @18432 B, Vh @36864 B — 55296 B total.
// ---------------------------------------------------------------------------
#define ATTN_SMEM 55296

__global__ __launch_bounds__(256, 2) void k_attn() {
    extern __shared__ __half smh[];
    __half* Qh = smh;              // [128][72] halves
    __half* Kh = smh + 9216;       // byte 18432
    const uint32_t sb = smem_to_u32(smh);
    const uint32_t vb = sb + 36864;    // Vh base (bytes)

    const int h = blockIdx.x, w = blockIdx.y;
    const int tid  = threadIdx.x;
    const int warp = tid >> 5, lane = tid & 31;
    const int gid = lane >> 2, tq = lane & 3;

    const size_t part = (size_t)NWIN * NHEADS * WIN * HD;
    const size_t bq = ((size_t)w * NHEADS + h) * (WIN * HD);

    {   // cp.async loads: 2 threads per row, 32 halves (4 x 16B) per array.
        const int r = tid >> 1;
        const uint32_t rb = (uint32_t)(r * 144 + (tid & 1) * 64);
        const size_t so = bq + (size_t)r * HD + (tid & 1) * 32;
#pragma unroll
        for (int q = 0; q < 4; q++) {
            CP_ASYNC16(sb + rb + q * 16,         g_qkv_hi + so + q * 8);          // Q
            CP_ASYNC16(sb + 18432 + rb + q * 16, g_qkv_hi + part + so + q * 8);   // K
        }
        CP_COMMIT();
#pragma unroll
        for (int q = 0; q < 4; q++)
            CP_ASYNC16(vb + rb + q * 16, g_qkv_hi + 2 * part + so + q * 8);       // V
        CP_COMMIT();
    }
    CP_WAIT(1);
    __syncthreads();           // Q + K visible; V still in flight

    // ---- S = (Q/8) K^T (rows 16w..16w+15 x 128 keys), fp32 regs ----
    const int r0 = warp * 16 + gid;
    uint32_t qa[4][4];
#pragma unroll
    for (int k = 0; k < 4; k++) {
        qa[k][0] = *(const uint32_t*)&Qh[(r0)     * 72 + k * 16 + tq * 2];
        qa[k][1] = *(const uint32_t*)&Qh[(r0 + 8) * 72 + k * 16 + tq * 2];
        qa[k][2] = *(const uint32_t*)&Qh[(r0)     * 72 + k * 16 + 8 + tq * 2];
        qa[k][3] = *(const uint32_t*)&Qh[(r0 + 8) * 72 + k * 16 + 8 + tq * 2];
    }
    float sacc[16][4];
#pragma unroll
    for (int t = 0; t < 16; t++)
#pragma unroll
        for (int e = 0; e < 4; e++) sacc[t][e] = 0.0f;

#pragma unroll
    for (int jn = 0; jn < 16; jn++) {
        const int nr = jn * 8 + gid;
#pragma unroll
        for (int k = 0; k < 4; k++) {
            uint32_t b0 = *(const uint32_t*)&Kh[nr * 72 + k * 16 + tq * 2];
            uint32_t b1 = *(const uint32_t*)&Kh[nr * 72 + k * 16 + 8 + tq * 2];
            mma16816(sacc[jn], qa[k][0], qa[k][1], qa[k][2], qa[k][3], b0, b1);
        }
    }

    // ---- softmax (rows r0, r0+8); 4-lane shfl reductions ----
    float m0 = -1e30f, m1 = -1e30f;
#pragma unroll
    for (int t = 0; t < 16; t++) {
        m0 = fmaxf(m0, fmaxf(sacc[t][0], sacc[t][1]));
        m1 = fmaxf(m1, fmaxf(sacc[t][2], sacc[t][3]));
    }
    m0 = fmaxf(m0, __shfl_xor_sync(0xffffffffu, m0, 1));
    m0 = fmaxf(m0, __shfl_xor_sync(0xffffffffu, m0, 2));
    m1 = fmaxf(m1, __shfl_xor_sync(0xffffffffu, m1, 1));
    m1 = fmaxf(m1, __shfl_xor_sync(0xffffffffu, m1, 2));

    float s0 = 0.0f, s1 = 0.0f;
#pragma unroll
    for (int t = 0; t < 16; t++) {
        sacc[t][0] = __expf(sacc[t][0] - m0);
        sacc[t][1] = __expf(sacc[t][1] - m0);
        sacc[t][2] = __expf(sacc[t][2] - m1);
        sacc[t][3] = __expf(sacc[t][3] - m1);
        s0 += sacc[t][0] + sacc[t][1];
        s1 += sacc[t][2] + sacc[t][3];
    }
    s0 += __shfl_xor_sync(0xffffffffu, s0, 1);
    s0 += __shfl_xor_sync(0xffffffffu, s0, 2);
    s1 += __shfl_xor_sync(0xffffffffu, s1, 1);
    s1 += __shfl_xor_sync(0xffffffffu, s1, 2);
    const float inv0 = 1.0f / s0, inv1 = 1.0f / s1;

    uint32_t ph0[16], ph1[16];     // P as f16x2; C-layout == A-layout of PV mma
#pragma unroll
    for (int t = 0; t < 16; t++) {
        __half2 p0 = __floats2half2_rn(sacc[t][0] * inv0, sacc[t][1] * inv0);
        __half2 p1 = __floats2half2_rn(sacc[t][2] * inv1, sacc[t][3] * inv1);
        ph0[t] = *reinterpret_cast<uint32_t*>(&p0);
        ph1[t] = *reinterpret_cast<uint32_t*>(&p1);
    }

    CP_WAIT(0);
    __syncthreads();           // V visible to all warps

    // ---- O = P V : 8 k-steps (k16) x 8 n8-tiles; V via ldmatrix.x2.trans ----
    float oacc[8][4];
#pragma unroll
    for (int jn = 0; jn < 8; jn++)
#pragma unroll
        for (int e = 0; e < 4; e++) oacc[jn][e] = 0.0f;

    const int ll = lane & 15;
#pragma unroll
    for (int kk = 0; kk < 8; kk++) {
        const uint32_t a0 = ph0[2 * kk],     a1 = ph1[2 * kk];
        const uint32_t a2 = ph0[2 * kk + 1], a3 = ph1[2 * kk + 1];
        const uint32_t rowa = vb + (uint32_t)((kk * 16 + ll) * 144);
#pragma unroll
        for (int jn = 0; jn < 8; jn++) {
            uint32_t b0, b1;
            ldmx2t(b0, b1, rowa + jn * 16);
            mma16816(oacc[jn], a0, a1, a2, a3, b0, b1);
        }
    }

    // ---- stage O into (dead, warp-private) Qh rows, then coalesced store ----
#pragma unroll
    for (int jn = 0; jn < 8; jn++) {
        __half2 o0 = __floats2half2_rn(oacc[jn][0], oacc[jn][1]);
        __half2 o1 = __floats2half2_rn(oacc[jn][2], oacc[jn][3]);
        *(__half2*)&Qh[(r0)     * 72 + jn * 8 + tq * 2] = o0;
        *(__half2*)&Qh[(r0 + 8) * 72 + jn * 8 + tq * 2] = o1;
    }
    __syncwarp();

    const size_t obase = ((size_t)w * WIN + warp * 16) * DMODEL + h * HD;
#pragma unroll
    for (int it = 0; it < 4; it++) {
        int idx = lane + it * 32;          // 16 rows x 8 chunks of 16B
        int r = idx >> 3, ch = idx & 7;
        uint4 v = *(const uint4*)&Qh[(warp * 16 + r) * 72 + ch * 8];
        *(uint4*)(g_o_hi + obase + (size_t)r * DMODEL + ch * 8) = v;
    }
}

// ---------------------------------------------------------------------------
extern "C" void kernel_launch(void* const* d_in, const int* in_sizes, int n_in,
                              void* d_out, int out_size) {
    const float* x     = (const float*)d_in[0];
    const float* w_in  = (const float*)d_in[1];
    const float* b_in  = (const float*)d_in[2];
    const float* w_out = (const float*)d_in[3];
    const float* b_out = (const float*)d_in[4];
    float* out = (float*)d_out;

    cudaFuncSetAttribute(k_proj<0>, cudaFuncAttributeMaxDynamicSharedMemorySize, PROJ_SMEM);
    cudaFuncSetAttribute(k_proj<1>, cudaFuncAttributeMaxDynamicSharedMemorySize, PROJ_SMEM);
    cudaFuncSetAttribute(k_attn,    cudaFuncAttributeMaxDynamicSharedMemorySize, ATTN_SMEM);

    k_split_all<<<(N4ALL / 2 + 255) / 256, 256>>>((const float4*)x, (const float4*)w_in,
                                                  (const float4*)w_out);

    k_proj<0><<<dim3(6, NWIN), 512, PROJ_SMEM>>>(b_in, nullptr);
    k_attn<<<dim3(NHEADS, NWIN), 256, ATTN_SMEM>>>();
    k_proj<1><<<dim3(2, NWIN), 512, PROJ_SMEM>>>(b_out, out);
}

// round 16
// speedup vs baseline: 1.0132x; 1.0132x over previous
#include <cuda_runtime.h>
#include <cuda_fp16.h>
#include <mma.h>
#include <cstdint>
using namespace nvcuda;

// Problem constants (fixed by setup_inputs)
#define BATCH   32
#define SLEN    4096
#define DMODEL  512
#define NHEADS  8
#define HD      64
#define WIN     128
#define SHIFT   64
#define NWIN    1024          // total windows (BATCH * 32)

// ---------------------------------------------------------------------------
// Persistent fp16 arrays — all hi-only (calibrated rel_err ~7.0e-4).
// Q part of g_qkv_hi is pre-scaled by 0.125 (exact power-of-2 fold).
// ---------------------------------------------------------------------------
__device__ __align__(16) __half g_x_hi[(size_t)BATCH * SLEN * DMODEL];
__device__ __align__(16) __half g_win_hi[3 * DMODEL * DMODEL];
__device__ __align__(16) __half g_wout_hi[DMODEL * DMODEL];
__device__ __align__(16) __half g_qkv_hi[(size_t)3 * NWIN * NHEADS * WIN * HD];
__device__ __align__(16) __half g_o_hi[(size_t)NWIN * WIN * DMODEL];

// ---------------------------------------------------------------------------
// wmma fp16 types (projections only)
// ---------------------------------------------------------------------------
using HA  = wmma::fragment<wmma::matrix_a, 16, 16, 16, __half, wmma::row_major>;
using HBc = wmma::fragment<wmma::matrix_b, 16, 16, 16, __half, wmma::col_major>;
using CF  = wmma::fragment<wmma::accumulator, 16, 16, 16, float>;

__device__ __forceinline__ void hi_store4(const float4 v, __half* hi) {
    *reinterpret_cast<__half2*>(hi)     = __halves2half2(__float2half_rn(v.x), __float2half_rn(v.y));
    *reinterpret_cast<__half2*>(hi + 2) = __halves2half2(__float2half_rn(v.z), __float2half_rn(v.w));
}

// ---------------------------------------------------------------------------
// PTX helpers
// ---------------------------------------------------------------------------
__device__ __forceinline__ uint32_t smem_to_u32(const void* p) {
    uint32_t a;
    asm("{ .reg .u64 t; cvta.to.shared.u64 t, %1; cvt.u32.u64 %0, t; }" : "=r"(a) : "l"(p));
    return a;
}
#define CP_ASYNC16(su32, gptr) \
    asm volatile("cp.async.cg.shared.global [%0], [%1], 16;" :: "r"(su32), "l"(gptr) : "memory")
#define CP_COMMIT() asm volatile("cp.async.commit_group;" ::: "memory")
#define CP_WAIT(n)  asm volatile("cp.async.wait_group %0;" :: "n"(n) : "memory")

__device__ __forceinline__ void mma16816(float c[4], uint32_t a0, uint32_t a1,
                                         uint32_t a2, uint32_t a3,
                                         uint32_t b0, uint32_t b1) {
    asm volatile(
        "mma.sync.aligned.m16n8k16.row.col.f32.f16.f16.f32 "
        "{%0,%1,%2,%3}, {%4,%5,%6,%7}, {%8,%9}, {%0,%1,%2,%3};"
        : "+f"(c[0]), "+f"(c[1]), "+f"(c[2]), "+f"(c[3])
        : "r"(a0), "r"(a1), "r"(a2), "r"(a3), "r"(b0), "r"(b1));
}
__device__ __forceinline__ void ldmx2t(uint32_t& r0, uint32_t& r1, uint32_t saddr) {
    asm volatile("ldmatrix.sync.aligned.m8n8.x2.trans.shared.b16 {%0,%1}, [%2];"
                 : "=r"(r0), "=r"(r1) : "r"(saddr));
}

// ---------------------------------------------------------------------------
// Prep splits, single merged launch; dense 1 float4 per thread (coalesced),
// streaming loads (read-once data, evict-first).
// ---------------------------------------------------------------------------
#define N4X  (BATCH * SLEN * DMODEL / 4)        // 16,777,216
#define N4WI (3 * DMODEL * DMODEL / 4)          // 196,608
#define N4WO (DMODEL * DMODEL / 4)              // 65,536
#define N4ALL (N4X + N4WI + N4WO)

__global__ void k_split_all(const float4* __restrict__ x,
                            const float4* __restrict__ w_in,
                            const float4* __restrict__ w_out) {
    int i = blockIdx.x * blockDim.x + threadIdx.x;
    if (i >= N4ALL) return;
    if (i < N4X) {
        hi_store4(__ldcs(&x[i]), g_x_hi + (size_t)i * 4);
    } else if (i < N4X + N4WI) {
        int k = i - N4X;
        hi_store4(__ldcs(&w_in[k]), g_win_hi + (size_t)k * 4);
    } else {
        int k = i - N4X - N4WI;
        hi_store4(__ldcs(&w_out[k]), g_wout_hi + (size_t)k * 4);
    }
}

// ---------------------------------------------------------------------------
// Projection GEMM (frozen R7/R9 config): C[128x256] per CTA = Ah@Bh^T,
// cp.async 3-stage, 512 threads, warp grid 4x4, warp tile 32x64.
// MODE 0: A = rolled x, B = w_in -> g_qkv_hi (Q block pre-scaled 0.125), +b_in
// MODE 1: A = g_o_hi,  B = w_out -> fp32 out with roll(+shift), +b_out
// ---------------------------------------------------------------------------
#define STG_BYTES 55296
#define PROJ_SMEM (3 * STG_BYTES)

template <int MODE>
__global__ __launch_bounds__(512, 1) void k_proj(const float* __restrict__ bias,
                                                 float* __restrict__ outp) {
    extern __shared__ char smem[];
    const uint32_t sb0 = smem_to_u32(smem);
    float* Cs = (float*)smem;              // [128][264]

    const int tid  = threadIdx.x;
    const int warp = tid >> 5;
    const int wr = warp >> 2, wc = warp & 3;
    const int n0 = blockIdx.x * 256;
    const int w  = blockIdx.y;
    const int b  = w >> 5, j = w & 31;

    const __half* Asrc_h = (MODE == 0) ? g_x_hi : g_o_hi;
    const __half* Bsrc_h = (MODE == 0) ? g_win_hi : g_wout_hi;

    const size_t abase = (MODE == 0) ? ((size_t)b * SLEN) * DMODEL
                                     : ((size_t)w * WIN) * DMODEL;

    CF acc[2][4];
#pragma unroll
    for (int i = 0; i < 2; i++)
#pragma unroll
        for (int jj = 0; jj < 4; jj++) wmma::fill_fragment(acc[i][jj], 0.0f);

    auto load_chunk = [&](int c, int st) {
        const uint32_t sbase = sb0 + st * STG_BYTES;
        const size_t g = (size_t)c * 64;
#pragma unroll
        for (int q = 0; q < 2; q++) {          // A: 128 rows x 8 c16
            int idx = tid + q * 512;
            int row = idx >> 3, c16 = idx & 7;
            size_t ar;
            if (MODE == 0) {
                int sp = (j * WIN + row + SHIFT) & (SLEN - 1);   // roll(-shift)
                ar = abase + (size_t)sp * DMODEL + g + c16 * 8;
            } else {
                ar = abase + (size_t)row * DMODEL + g + c16 * 8;
            }
            CP_ASYNC16(sbase + (uint32_t)(row * 144 + c16 * 16), Asrc_h + ar);
        }
#pragma unroll
        for (int q = 0; q < 4; q++) {          // B: 256 rows x 8 c16
            int idx = tid + q * 512;
            int row = idx >> 3, c16 = idx & 7;
            size_t br = (size_t)(n0 + row) * DMODEL + g + c16 * 8;
            CP_ASYNC16(sbase + 18432 + (uint32_t)(row * 144 + c16 * 16), Bsrc_h + br);
        }
        CP_COMMIT();
    };

    load_chunk(0, 0);
    load_chunk(1, 1);

    for (int c = 0; c < 8; c++) {
        if (c < 7) CP_WAIT(1); else CP_WAIT(0);
        __syncthreads();
        if (c + 2 < 8) load_chunk(c + 2, (c + 2) % 3);

        const __half* Ah = (const __half*)(smem + (c % 3) * STG_BYTES);
        const __half* Bh = Ah + 9216;
#pragma unroll
        for (int ks = 0; ks < 4; ks++) {
            HA ah[2];
#pragma unroll
            for (int i = 0; i < 2; i++)
                wmma::load_matrix_sync(ah[i], Ah + (wr * 32 + i * 16) * 72 + ks * 16, 72);
#pragma unroll
            for (int jj = 0; jj < 4; jj++) {
                HBc bh;
                wmma::load_matrix_sync(bh, Bh + (wc * 64 + jj * 16) * 72 + ks * 16, 72);
#pragma unroll
                for (int i = 0; i < 2; i++)
                    wmma::mma_sync(acc[i][jj], ah[i], bh, acc[i][jj]);
            }
        }
    }
    __syncthreads();

#pragma unroll
    for (int i = 0; i < 2; i++)
#pragma unroll
        for (int jj = 0; jj < 4; jj++)
            wmma::store_matrix_sync(Cs + (wr * 32 + i * 16) * 264 + wc * 64 + jj * 16,
                                    acc[i][jj], 264, wmma::mem_row_major);
    __syncthreads();

#pragma unroll
    for (int it = 0; it < 16; it++) {
        int idx = tid + it * 512;
        int r = idx >> 6, cc = (idx & 63) * 4;
        float4 v;
        v.x = Cs[r * 264 + cc + 0] + bias[n0 + cc + 0];
        v.y = Cs[r * 264 + cc + 1] + bias[n0 + cc + 1];
        v.z = Cs[r * 264 + cc + 2] + bias[n0 + cc + 2];
        v.w = Cs[r * 264 + cc + 3] + bias[n0 + cc + 3];
        if (MODE == 0) {
            int gc = n0 + cc;
            int p = gc >> 9, hh = (gc >> 6) & 7, d = gc & 63;
            if (p == 0) {      // fold 1/sqrt(hd)=0.125 into Q (exact pow-2)
                v.x *= 0.125f; v.y *= 0.125f; v.z *= 0.125f; v.w *= 0.125f;
            }
            size_t o = ((((size_t)p * NWIN + w) * NHEADS + hh) * WIN + r) * HD + d;
            hi_store4(v, g_qkv_hi + o);
        } else {
            int sp = (j * WIN + r + SHIFT) & (SLEN - 1);   // roll(+shift)
            *(float4*)(outp + ((size_t)b * SLEN + sp) * DMODEL + n0 + cc) = v;
        }
    }
}

// ---------------------------------------------------------------------------
// Attention — register-resident softmax (PTX mma.m16n8k16, FA2-style).
// One CTA per (head, window), 256 threads (8 warps), 2 CTAs/SM.
// Q arrives pre-scaled by 0.125 (folded at proj0) -> no scale loop here.
// smem: Qh [128][72] @0, Kh @18432 B, Vh @36864 B — 55296 B total.
// ---------------------------------------------------------------------------
#define ATTN_SMEM 55296

__global__ __launch_bounds__(256, 2) void k_attn() {
    extern __shared__ __half smh[];
    __half* Qh = smh;              // [128][72] halves
    __half* Kh = smh + 9216;       // byte 18432
    const uint32_t sb = smem_to_u32(smh);
    const uint32_t vb = sb + 36864;    // Vh base (bytes)

    const int h = blockIdx.x, w = blockIdx.y;
    const int tid  = threadIdx.x;
    const int warp = tid >> 5, lane = tid & 31;
    const int gid = lane >> 2, tq = lane & 3;

    const size_t part = (size_t)NWIN * NHEADS * WIN * HD;
    const size_t bq = ((size_t)w * NHEADS + h) * (WIN * HD);

    {   // cp.async loads: 2 threads per row, 32 halves (4 x 16B) per array.
        const int r = tid >> 1;
        const uint32_t rb = (uint32_t)(r * 144 + (tid & 1) * 64);
        const size_t so = bq + (size_t)r * HD + (tid & 1) * 32;
#pragma unroll
        for (int q = 0; q < 4; q++) {
            CP_ASYNC16(sb + rb + q * 16,         g_qkv_hi + so + q * 8);          // Q
            CP_ASYNC16(sb + 18432 + rb + q * 16, g_qkv_hi + part + so + q * 8);   // K
        }
        CP_COMMIT();
#pragma unroll
        for (int q = 0; q < 4; q++)
            CP_ASYNC16(vb + rb + q * 16, g_qkv_hi + 2 * part + so + q * 8);       // V
        CP_COMMIT();
    }
    CP_WAIT(1);
    __syncthreads();           // Q + K visible; V still in flight

    // ---- S = (Q/8) K^T (rows 16w..16w+15 x 128 keys), fp32 regs ----
    const int r0 = warp * 16 + gid;
    uint32_t qa[4][4];
#pragma unroll
    for (int k = 0; k < 4; k++) {
        qa[k][0] = *(const uint32_t*)&Qh[(r0)     * 72 + k * 16 + tq * 2];
        qa[k][1] = *(const uint32_t*)&Qh[(r0 + 8) * 72 + k * 16 + tq * 2];
        qa[k][2] = *(const uint32_t*)&Qh[(r0)     * 72 + k * 16 + 8 + tq * 2];
        qa[k][3] = *(const uint32_t*)&Qh[(r0 + 8) * 72 + k * 16 + 8 + tq * 2];
    }
    float sacc[16][4];
#pragma unroll
    for (int t = 0; t < 16; t++)
#pragma unroll
        for (int e = 0; e < 4; e++) sacc[t][e] = 0.0f;

#pragma unroll
    for (int jn = 0; jn < 16; jn++) {
        const int nr = jn * 8 + gid;
#pragma unroll
        for (int k = 0; k < 4; k++) {
            uint32_t b0 = *(const uint32_t*)&Kh[nr * 72 + k * 16 + tq * 2];
            uint32_t b1 = *(const uint32_t*)&Kh[nr * 72 + k * 16 + 8 + tq * 2];
            mma16816(sacc[jn], qa[k][0], qa[k][1], qa[k][2], qa[k][3], b0, b1);
        }
    }

    // ---- softmax (rows r0, r0+8); 4-lane shfl reductions ----
    float m0 = -1e30f, m1 = -1e30f;
#pragma unroll
    for (int t = 0; t < 16; t++) {
        m0 = fmaxf(m0, fmaxf(sacc[t][0], sacc[t][1]));
        m1 = fmaxf(m1, fmaxf(sacc[t][2], sacc[t][3]));
    }
    m0 = fmaxf(m0, __shfl_xor_sync(0xffffffffu, m0, 1));
    m0 = fmaxf(m0, __shfl_xor_sync(0xffffffffu, m0, 2));
    m1 = fmaxf(m1, __shfl_xor_sync(0xffffffffu, m1, 1));
    m1 = fmaxf(m1, __shfl_xor_sync(0xffffffffu, m1, 2));

    float s0 = 0.0f, s1 = 0.0f;
#pragma unroll
    for (int t = 0; t < 16; t++) {
        sacc[t][0] = __expf(sacc[t][0] - m0);
        sacc[t][1] = __expf(sacc[t][1] - m0);
        sacc[t][2] = __expf(sacc[t][2] - m1);
        sacc[t][3] = __expf(sacc[t][3] - m1);
        s0 += sacc[t][0] + sacc[t][1];
        s1 += sacc[t][2] + sacc[t][3];
    }
    s0 += __shfl_xor_sync(0xffffffffu, s0, 1);
    s0 += __shfl_xor_sync(0xffffffffu, s0, 2);
    s1 += __shfl_xor_sync(0xffffffffu, s1, 1);
    s1 += __shfl_xor_sync(0xffffffffu, s1, 2);
    const float inv0 = 1.0f / s0, inv1 = 1.0f / s1;

    uint32_t ph0[16], ph1[16];     // P as f16x2; C-layout == A-layout of PV mma
#pragma unroll
    for (int t = 0; t < 16; t++) {
        __half2 p0 = __floats2half2_rn(sacc[t][0] * inv0, sacc[t][1] * inv0);
        __half2 p1 = __floats2half2_rn(sacc[t][2] * inv1, sacc[t][3] * inv1);
        ph0[t] = *reinterpret_cast<uint32_t*>(&p0);
        ph1[t] = *reinterpret_cast<uint32_t*>(&p1);
    }

    CP_WAIT(0);
    __syncthreads();           // V visible to all warps

    // ---- O = P V : 8 k-steps (k16) x 8 n8-tiles; V via ldmatrix.x2.trans ----
    float oacc[8][4];
#pragma unroll
    for (int jn = 0; jn < 8; jn++)
#pragma unroll
        for (int e = 0; e < 4; e++) oacc[jn][e] = 0.0f;

    const int ll = lane & 15;
#pragma unroll
    for (int kk = 0; kk < 8; kk++) {
        const uint32_t a0 = ph0[2 * kk],     a1 = ph1[2 * kk];
        const uint32_t a2 = ph0[2 * kk + 1], a3 = ph1[2 * kk + 1];
        const uint32_t rowa = vb + (uint32_t)((kk * 16 + ll) * 144);
#pragma unroll
        for (int jn = 0; jn < 8; jn++) {
            uint32_t b0, b1;
            ldmx2t(b0, b1, rowa + jn * 16);
            mma16816(oacc[jn], a0, a1, a2, a3, b0, b1);
        }
    }

    // ---- stage O into (dead, warp-private) Qh rows, then coalesced store ----
#pragma unroll
    for (int jn = 0; jn < 8; jn++) {
        __half2 o0 = __floats2half2_rn(oacc[jn][0], oacc[jn][1]);
        __half2 o1 = __floats2half2_rn(oacc[jn][2], oacc[jn][3]);
        *(__half2*)&Qh[(r0)     * 72 + jn * 8 + tq * 2] = o0;
        *(__half2*)&Qh[(r0 + 8) * 72 + jn * 8 + tq * 2] = o1;
    }
    __syncwarp();

    const size_t obase = ((size_t)w * WIN + warp * 16) * DMODEL + h * HD;
#pragma unroll
    for (int it = 0; it < 4; it++) {
        int idx = lane + it * 32;          // 16 rows x 8 chunks of 16B
        int r = idx >> 3, ch = idx & 7;
        uint4 v = *(const uint4*)&Qh[(warp * 16 + r) * 72 + ch * 8];
        *(uint4*)(g_o_hi + obase + (size_t)r * DMODEL + ch * 8) = v;
    }
}

// ---------------------------------------------------------------------------
extern "C" void kernel_launch(void* const* d_in, const int* in_sizes, int n_in,
                              void* d_out, int out_size) {
    const float* x     = (const float*)d_in[0];
    const float* w_in  = (const float*)d_in[1];
    const float* b_in  = (const float*)d_in[2];
    const float* w_out = (const float*)d_in[3];
    const float* b_out = (const float*)d_in[4];
    float* out = (float*)d_out;

    cudaFuncSetAttribute(k_proj<0>, cudaFuncAttributeMaxDynamicSharedMemorySize, PROJ_SMEM);
    cudaFuncSetAttribute(k_proj<1>, cudaFuncAttributeMaxDynamicSharedMemorySize, PROJ_SMEM);
    cudaFuncSetAttribute(k_attn,    cudaFuncAttributeMaxDynamicSharedMemorySize, ATTN_SMEM);

    k_split_all<<<(N4ALL + 255) / 256, 256>>>((const float4*)x, (const float4*)w_in,
                                              (const float4*)w_out);

    k_proj<0><<<dim3(6, NWIN), 512, PROJ_SMEM>>>(b_in, nullptr);
    k_attn<<<dim3(NHEADS, NWIN), 256, ATTN_SMEM>>>();
    k_proj<1><<<dim3(2, NWIN), 512, PROJ_SMEM>>>(b_out, out);
}

// round 17
// speedup vs baseline: 1.0147x; 1.0015x over previous
#include <cuda_runtime.h>
#include <cuda_fp16.h>
#include <mma.h>
#include <cstdint>
using namespace nvcuda;

// Problem constants (fixed by setup_inputs)
#define BATCH   32
#define SLEN    4096
#define DMODEL  512
#define NHEADS  8
#define HD      64
#define WIN     128
#define SHIFT   64
#define NWIN    1024          // total windows (BATCH * 32)

// ---------------------------------------------------------------------------
// Persistent fp16 arrays — all hi-only (calibrated rel_err ~7.0e-4).
// Q part of g_qkv_hi is pre-scaled by 0.125 (exact power-of-2 fold).
// ---------------------------------------------------------------------------
__device__ __align__(16) __half g_x_hi[(size_t)BATCH * SLEN * DMODEL];
__device__ __align__(16) __half g_win_hi[3 * DMODEL * DMODEL];
__device__ __align__(16) __half g_wout_hi[DMODEL * DMODEL];
__device__ __align__(16) __half g_qkv_hi[(size_t)3 * NWIN * NHEADS * WIN * HD];
__device__ __align__(16) __half g_o_hi[(size_t)NWIN * WIN * DMODEL];

// ---------------------------------------------------------------------------
// wmma fp16 types (projections only)
// ---------------------------------------------------------------------------
using HA  = wmma::fragment<wmma::matrix_a, 16, 16, 16, __half, wmma::row_major>;
using HBc = wmma::fragment<wmma::matrix_b, 16, 16, 16, __half, wmma::col_major>;
using CF  = wmma::fragment<wmma::accumulator, 16, 16, 16, float>;

__device__ __forceinline__ void hi_store4(const float4 v, __half* hi) {
    *reinterpret_cast<__half2*>(hi)     = __halves2half2(__float2half_rn(v.x), __float2half_rn(v.y));
    *reinterpret_cast<__half2*>(hi + 2) = __halves2half2(__float2half_rn(v.z), __float2half_rn(v.w));
}

// ---------------------------------------------------------------------------
// PTX helpers
// ---------------------------------------------------------------------------
__device__ __forceinline__ uint32_t smem_to_u32(const void* p) {
    uint32_t a;
    asm("{ .reg .u64 t; cvta.to.shared.u64 t, %1; cvt.u32.u64 %0, t; }" : "=r"(a) : "l"(p));
    return a;
}
#define CP_ASYNC16(su32, gptr) \
    asm volatile("cp.async.cg.shared.global [%0], [%1], 16;" :: "r"(su32), "l"(gptr) : "memory")
#define CP_COMMIT() asm volatile("cp.async.commit_group;" ::: "memory")
#define CP_WAIT(n)  asm volatile("cp.async.wait_group %0;" :: "n"(n) : "memory")

__device__ __forceinline__ void mma16816(float c[4], uint32_t a0, uint32_t a1,
                                         uint32_t a2, uint32_t a3,
                                         uint32_t b0, uint32_t b1) {
    asm volatile(
        "mma.sync.aligned.m16n8k16.row.col.f32.f16.f16.f32 "
        "{%0,%1,%2,%3}, {%4,%5,%6,%7}, {%8,%9}, {%0,%1,%2,%3};"
        : "+f"(c[0]), "+f"(c[1]), "+f"(c[2]), "+f"(c[3])
        : "r"(a0), "r"(a1), "r"(a2), "r"(a3), "r"(b0), "r"(b1));
}
__device__ __forceinline__ void ldmx2t(uint32_t& r0, uint32_t& r1, uint32_t saddr) {
    asm volatile("ldmatrix.sync.aligned.m8n8.x2.trans.shared.b16 {%0,%1}, [%2];"
                 : "=r"(r0), "=r"(r1) : "r"(saddr));
}

// ---------------------------------------------------------------------------
// Prep splits, single merged launch; dense 1 float4 per thread (coalesced),
// streaming loads (read-once data, evict-first).
// ---------------------------------------------------------------------------
#define N4X  (BATCH * SLEN * DMODEL / 4)        // 16,777,216
#define N4WI (3 * DMODEL * DMODEL / 4)          // 196,608
#define N4WO (DMODEL * DMODEL / 4)              // 65,536
#define N4ALL (N4X + N4WI + N4WO)

__global__ void k_split_all(const float4* __restrict__ x,
                            const float4* __restrict__ w_in,
                            const float4* __restrict__ w_out) {
    int i = blockIdx.x * blockDim.x + threadIdx.x;
    if (i >= N4ALL) return;
    if (i < N4X) {
        hi_store4(__ldcs(&x[i]), g_x_hi + (size_t)i * 4);
    } else if (i < N4X + N4WI) {
        int k = i - N4X;
        hi_store4(__ldcs(&w_in[k]), g_win_hi + (size_t)k * 4);
    } else {
        int k = i - N4X - N4WI;
        hi_store4(__ldcs(&w_out[k]), g_wout_hi + (size_t)k * 4);
    }
}

// ---------------------------------------------------------------------------
// Projection GEMM (frozen R7/R9 config): C[128x256] per CTA = Ah@Bh^T,
// cp.async 3-stage, 512 threads, warp grid 4x4, warp tile 32x64.
// MODE 0: A = rolled x, B = w_in -> g_qkv_hi (Q block pre-scaled 0.125), +b_in
//         (Cs smem staging epilogue — fp16 conversion needs a known layout)
// MODE 1: A = g_o_hi,  B = w_out -> fp32 out with roll(+shift), +b_out
//         (NEW: direct fragment epilogue — bias loaded as accumulator
//          fragment from a 16-row-replicated smem tile, elementwise add,
//          store_matrix_sync straight to global. Every 16-row tile of the
//          rolled output is contiguous because the wrap point r=64 (window
//          j=31) is 16-aligned.)
// ---------------------------------------------------------------------------
#define STG_BYTES 55296
#define PROJ_SMEM (3 * STG_BYTES)

template <int MODE>
__global__ __launch_bounds__(512, 1) void k_proj(const float* __restrict__ bias,
                                                 float* __restrict__ outp) {
    extern __shared__ char smem[];
    const uint32_t sb0 = smem_to_u32(smem);
    float* Cs = (float*)smem;              // [128][264] (MODE 0 epilogue)

    const int tid  = threadIdx.x;
    const int warp = tid >> 5;
    const int wr = warp >> 2, wc = warp & 3;
    const int n0 = blockIdx.x * 256;
    const int w  = blockIdx.y;
    const int b  = w >> 5, j = w & 31;

    const __half* Asrc_h = (MODE == 0) ? g_x_hi : g_o_hi;
    const __half* Bsrc_h = (MODE == 0) ? g_win_hi : g_wout_hi;

    const size_t abase = (MODE == 0) ? ((size_t)b * SLEN) * DMODEL
                                     : ((size_t)w * WIN) * DMODEL;

    CF acc[2][4];
#pragma unroll
    for (int i = 0; i < 2; i++)
#pragma unroll
        for (int jj = 0; jj < 4; jj++) wmma::fill_fragment(acc[i][jj], 0.0f);

    auto load_chunk = [&](int c, int st) {
        const uint32_t sbase = sb0 + st * STG_BYTES;
        const size_t g = (size_t)c * 64;
#pragma unroll
        for (int q = 0; q < 2; q++) {          // A: 128 rows x 8 c16
            int idx = tid + q * 512;
            int row = idx >> 3, c16 = idx & 7;
            size_t ar;
            if (MODE == 0) {
                int sp = (j * WIN + row + SHIFT) & (SLEN - 1);   // roll(-shift)
                ar = abase + (size_t)sp * DMODEL + g + c16 * 8;
            } else {
                ar = abase + (size_t)row * DMODEL + g + c16 * 8;
            }
            CP_ASYNC16(sbase + (uint32_t)(row * 144 + c16 * 16), Asrc_h + ar);
        }
#pragma unroll
        for (int q = 0; q < 4; q++) {          // B: 256 rows x 8 c16
            int idx = tid + q * 512;
            int row = idx >> 3, c16 = idx & 7;
            size_t br = (size_t)(n0 + row) * DMODEL + g + c16 * 8;
            CP_ASYNC16(sbase + 18432 + (uint32_t)(row * 144 + c16 * 16), Bsrc_h + br);
        }
        CP_COMMIT();
    };

    load_chunk(0, 0);
    load_chunk(1, 1);

    for (int c = 0; c < 8; c++) {
        if (c < 7) CP_WAIT(1); else CP_WAIT(0);
        __syncthreads();
        if (c + 2 < 8) load_chunk(c + 2, (c + 2) % 3);

        const __half* Ah = (const __half*)(smem + (c % 3) * STG_BYTES);
        const __half* Bh = Ah + 9216;
#pragma unroll
        for (int ks = 0; ks < 4; ks++) {
            HA ah[2];
#pragma unroll
            for (int i = 0; i < 2; i++)
                wmma::load_matrix_sync(ah[i], Ah + (wr * 32 + i * 16) * 72 + ks * 16, 72);
#pragma unroll
            for (int jj = 0; jj < 4; jj++) {
                HBc bh;
                wmma::load_matrix_sync(bh, Bh + (wc * 64 + jj * 16) * 72 + ks * 16, 72);
#pragma unroll
                for (int i = 0; i < 2; i++)
                    wmma::mma_sync(acc[i][jj], ah[i], bh, acc[i][jj]);
            }
        }
    }
    __syncthreads();     // mainloop smem reads done; stages are dead now

    if (MODE == 0) {
        // ---- Cs staging epilogue (fp16 output needs known layout) ----
#pragma unroll
        for (int i = 0; i < 2; i++)
#pragma unroll
            for (int jj = 0; jj < 4; jj++)
                wmma::store_matrix_sync(Cs + (wr * 32 + i * 16) * 264 + wc * 64 + jj * 16,
                                        acc[i][jj], 264, wmma::mem_row_major);
        __syncthreads();

#pragma unroll
        for (int it = 0; it < 16; it++) {
            int idx = tid + it * 512;
            int r = idx >> 6, cc = (idx & 63) * 4;
            float4 v;
            v.x = Cs[r * 264 + cc + 0] + bias[n0 + cc + 0];
            v.y = Cs[r * 264 + cc + 1] + bias[n0 + cc + 1];
            v.z = Cs[r * 264 + cc + 2] + bias[n0 + cc + 2];
            v.w = Cs[r * 264 + cc + 3] + bias[n0 + cc + 3];
            int gc = n0 + cc;
            int p = gc >> 9, hh = (gc >> 6) & 7, d = gc & 63;
            if (p == 0) {      // fold 1/sqrt(hd)=0.125 into Q (exact pow-2)
                v.x *= 0.125f; v.y *= 0.125f; v.z *= 0.125f; v.w *= 0.125f;
            }
            size_t o = ((((size_t)p * NWIN + w) * NHEADS + hh) * WIN + r) * HD + d;
            hi_store4(v, g_qkv_hi + o);
        }
    } else {
        // ---- direct fragment epilogue (fp32 output) ----
        // Build 16-row replicated bias tile [16][264] in dead stage smem.
        float* Br = (float*)smem;
#pragma unroll
        for (int it = 0; it < 8; it++) {
            int idx = tid + it * 512;          // 16 x 256
            int r = idx >> 8, cc = idx & 255;
            Br[r * 264 + cc] = bias[n0 + cc];
        }
        __syncthreads();

#pragma unroll
        for (int jj = 0; jj < 4; jj++) {
            CF bf;
            wmma::load_matrix_sync(bf, Br + wc * 64 + jj * 16, 264, wmma::mem_row_major);
#pragma unroll
            for (int i = 0; i < 2; i++) {
#pragma unroll
                for (int e = 0; e < bf.num_elements; e++) acc[i][jj].x[e] += bf.x[e];
                int rr = wr * 32 + i * 16;
                int sp = (j * WIN + rr + SHIFT) & (SLEN - 1);   // tile-contiguous
                wmma::store_matrix_sync(outp + ((size_t)b * SLEN + sp) * DMODEL + n0
                                            + wc * 64 + jj * 16,
                                        acc[i][jj], DMODEL, wmma::mem_row_major);
            }
        }
    }
}

// ---------------------------------------------------------------------------
// Attention — register-resident softmax (PTX mma.m16n8k16, FA2-style).
// One CTA per (head, window), 256 threads (8 warps), 2 CTAs/SM.
// Q arrives pre-scaled by 0.125 (folded at proj0) -> no scale loop here.
// smem: Qh [128][72] @0, Kh @18432 B, Vh @36864 B — 55296 B total.
// ---------------------------------------------------------------------------
#define ATTN_SMEM 55296

__global__ __launch_bounds__(256, 2) void k_attn() {
    extern __shared__ __half smh[];
    __half* Qh = smh;              // [128][72] halves
    __half* Kh = smh + 9216;       // byte 18432
    const uint32_t sb = smem_to_u32(smh);
    const uint32_t vb = sb + 36864;    // Vh base (bytes)

    const int h = blockIdx.x, w = blockIdx.y;
    const int tid  = threadIdx.x;
    const int warp = tid >> 5, lane = tid & 31;
    const int gid = lane >> 2, tq = lane & 3;

    const size_t part = (size_t)NWIN * NHEADS * WIN * HD;
    const size_t bq = ((size_t)w * NHEADS + h) * (WIN * HD);

    {   // cp.async loads: 2 threads per row, 32 halves (4 x 16B) per array.
        const int r = tid >> 1;
        const uint32_t rb = (uint32_t)(r * 144 + (tid & 1) * 64);
        const size_t so = bq + (size_t)r * HD + (tid & 1) * 32;
#pragma unroll
        for (int q = 0; q < 4; q++) {
            CP_ASYNC16(sb + rb + q * 16,         g_qkv_hi + so + q * 8);          // Q
            CP_ASYNC16(sb + 18432 + rb + q * 16, g_qkv_hi + part + so + q * 8);   // K
        }
        CP_COMMIT();
#pragma unroll
        for (int q = 0; q < 4; q++)
            CP_ASYNC16(vb + rb + q * 16, g_qkv_hi + 2 * part + so + q * 8);       // V
        CP_COMMIT();
    }
    CP_WAIT(1);
    __syncthreads();           // Q + K visible; V still in flight

    // ---- S = (Q/8) K^T (rows 16w..16w+15 x 128 keys), fp32 regs ----
    const int r0 = warp * 16 + gid;
    uint32_t qa[4][4];
#pragma unroll
    for (int k = 0; k < 4; k++) {
        qa[k][0] = *(const uint32_t*)&Qh[(r0)     * 72 + k * 16 + tq * 2];
        qa[k][1] = *(const uint32_t*)&Qh[(r0 + 8) * 72 + k * 16 + tq * 2];
        qa[k][2] = *(const uint32_t*)&Qh[(r0)     * 72 + k * 16 + 8 + tq * 2];
        qa[k][3] = *(const uint32_t*)&Qh[(r0 + 8) * 72 + k * 16 + 8 + tq * 2];
    }
    float sacc[16][4];
#pragma unroll
    for (int t = 0; t < 16; t++)
#pragma unroll
        for (int e = 0; e < 4; e++) sacc[t][e] = 0.0f;

#pragma unroll
    for (int jn = 0; jn < 16; jn++) {
        const int nr = jn * 8 + gid;
#pragma unroll
        for (int k = 0; k < 4; k++) {
            uint32_t b0 = *(const uint32_t*)&Kh[nr * 72 + k * 16 + tq * 2];
            uint32_t b1 = *(const uint32_t*)&Kh[nr * 72 + k * 16 + 8 + tq * 2];
            mma16816(sacc[jn], qa[k][0], qa[k][1], qa[k][2], qa[k][3], b0, b1);
        }
    }

    // ---- softmax (rows r0, r0+8); 4-lane shfl reductions ----
    float m0 = -1e30f, m1 = -1e30f;
#pragma unroll
    for (int t = 0; t < 16; t++) {
        m0 = fmaxf(m0, fmaxf(sacc[t][0], sacc[t][1]));
        m1 = fmaxf(m1, fmaxf(sacc[t][2], sacc[t][3]));
    }
    m0 = fmaxf(m0, __shfl_xor_sync(0xffffffffu, m0, 1));
    m0 = fmaxf(m0, __shfl_xor_sync(0xffffffffu, m0, 2));
    m1 = fmaxf(m1, __shfl_xor_sync(0xffffffffu, m1, 1));
    m1 = fmaxf(m1, __shfl_xor_sync(0xffffffffu, m1, 2));

    float s0 = 0.0f, s1 = 0.0f;
#pragma unroll
    for (int t = 0; t < 16; t++) {
        sacc[t][0] = __expf(sacc[t][0] - m0);
        sacc[t][1] = __expf(sacc[t][1] - m0);
        sacc[t][2] = __expf(sacc[t][2] - m1);
        sacc[t][3] = __expf(sacc[t][3] - m1);
        s0 += sacc[t][0] + sacc[t][1];
        s1 += sacc[t][2] + sacc[t][3];
    }
    s0 += __shfl_xor_sync(0xffffffffu, s0, 1);
    s0 += __shfl_xor_sync(0xffffffffu, s0, 2);
    s1 += __shfl_xor_sync(0xffffffffu, s1, 1);
    s1 += __shfl_xor_sync(0xffffffffu, s1, 2);
    const float inv0 = 1.0f / s0, inv1 = 1.0f / s1;

    uint32_t ph0[16], ph1[16];     // P as f16x2; C-layout == A-layout of PV mma
#pragma unroll
    for (int t = 0; t < 16; t++) {
        __half2 p0 = __floats2half2_rn(sacc[t][0] * inv0, sacc[t][1] * inv0);
        __half2 p1 = __floats2half2_rn(sacc[t][2] * inv1, sacc[t][3] * inv1);
        ph0[t] = *reinterpret_cast<uint32_t*>(&p0);
        ph1[t] = *reinterpret_cast<uint32_t*>(&p1);
    }

    CP_WAIT(0);
    __syncthreads();           // V visible to all warps

    // ---- O = P V : 8 k-steps (k16) x 8 n8-tiles; V via ldmatrix.x2.trans ----
    float oacc[8][4];
#pragma unroll
    for (int jn = 0; jn < 8; jn++)
#pragma unroll
        for (int e = 0; e < 4; e++) oacc[jn][e] = 0.0f;

    const int ll = lane & 15;
#pragma unroll
    for (int kk = 0; kk < 8; kk++) {
        const uint32_t a0 = ph0[2 * kk],     a1 = ph1[2 * kk];
        const uint32_t a2 = ph0[2 * kk + 1], a3 = ph1[2 * kk + 1];
        const uint32_t rowa = vb + (uint32_t)((kk * 16 + ll) * 144);
#pragma unroll
        for (int jn = 0; jn < 8; jn++) {
            uint32_t b0, b1;
            ldmx2t(b0, b1, rowa + jn * 16);
            mma16816(oacc[jn], a0, a1, a2, a3, b0, b1);
        }
    }

    // ---- stage O into (dead, warp-private) Qh rows, then coalesced store ----
#pragma unroll
    for (int jn = 0; jn < 8; jn++) {
        __half2 o0 = __floats2half2_rn(oacc[jn][0], oacc[jn][1]);
        __half2 o1 = __floats2half2_rn(oacc[jn][2], oacc[jn][3]);
        *(__half2*)&Qh[(r0)     * 72 + jn * 8 + tq * 2] = o0;
        *(__half2*)&Qh[(r0 + 8) * 72 + jn * 8 + tq * 2] = o1;
    }
    __syncwarp();

    const size_t obase = ((size_t)w * WIN + warp * 16) * DMODEL + h * HD;
#pragma unroll
    for (int it = 0; it < 4; it++) {
        int idx = lane + it * 32;          // 16 rows x 8 chunks of 16B
        int r = idx >> 3, ch = idx & 7;
        uint4 v = *(const uint4*)&Qh[(warp * 16 + r) * 72 + ch * 8];
        *(uint4*)(g_o_hi + obase + (size_t)r * DMODEL + ch * 8) = v;
    }
}

// ---------------------------------------------------------------------------
extern "C" void kernel_launch(void* const* d_in, const int* in_sizes, int n_in,
                              void* d_out, int out_size) {
    const float* x     = (const float*)d_in[0];
    const float* w_in  = (const float*)d_in[1];
    const float* b_in  = (const float*)d_in[2];
    const float* w_out = (const float*)d_in[3];
    const float* b_out = (const float*)d_in[4];
    float* out = (float*)d_out;

    cudaFuncSetAttribute(k_proj<0>, cudaFuncAttributeMaxDynamicSharedMemorySize, PROJ_SMEM);
    cudaFuncSetAttribute(k_proj<1>, cudaFuncAttributeMaxDynamicSharedMemorySize, PROJ_SMEM);
    cudaFuncSetAttribute(k_attn,    cudaFuncAttributeMaxDynamicSharedMemorySize, ATTN_SMEM);

    k_split_all<<<(N4ALL + 255) / 256, 256>>>((const float4*)x, (const float4*)w_in,
                                              (const float4*)w_out);

    k_proj<0><<<dim3(6, NWIN), 512, PROJ_SMEM>>>(b_in, nullptr);
    k_attn<<<dim3(NHEADS, NWIN), 256, ATTN_SMEM>>>();
    k_proj<1><<<dim3(2, NWIN), 512, PROJ_SMEM>>>(b_out, out);
}